// round 1
// baseline (speedup 1.0000x reference)
#include <cuda_runtime.h>
#include <math.h>

// ---------------- problem constants ----------------
// B=16, H=W=56, D=384, NH=12, HD=32, WS=7, SH=3, N=49, nW=64, L=3136
#define TOK   50176           // B*L  (also B*nW*N)
#define DIM   384
#define QKVD  1152
#define FFN   1536
#define EXPD  768

// ---------------- scratch ----------------
static __device__ float g_x  [TOK * DIM];     //  77 MB  working x
static __device__ float g_y  [TOK * DIM];     //  77 MB  LN outputs
static __device__ float g_o  [TOK * DIM];     //  77 MB  attention out
static __device__ float g_big[TOK * FFN];     // 308 MB  qkv / mlp-mid / expand

// window row -> token row (also token scatter for window reverse; same map)
__device__ __forceinline__ int map_row(int ridx, int shifted) {
    int n  = ridx % 49;
    int wi = (ridx / 49) & 63;
    int b  = ridx / (49 * 64);
    int r = n / 7, c = n % 7;
    int wh = wi >> 3, ww = wi & 7;
    int h = wh * 7 + r, w = ww * 7 + c;
    if (shifted) { h = (h + 3) % 56; w = (w + 3) % 56; }
    return b * 3136 + h * 56 + w;
}

__device__ __forceinline__ float block_sum(float v, float* sm) {
    #pragma unroll
    for (int o = 16; o; o >>= 1) v += __shfl_xor_sync(0xffffffffu, v, o);
    int w = threadIdx.x >> 5;
    if ((threadIdx.x & 31) == 0) sm[w] = v;
    __syncthreads();
    if (threadIdx.x < 32) {
        float u = (threadIdx.x < (blockDim.x >> 5)) ? sm[threadIdx.x] : 0.f;
        #pragma unroll
        for (int o = 16; o; o >>= 1) u += __shfl_xor_sync(0xffffffffu, u, o);
        if (threadIdx.x == 0) sm[0] = u;
    }
    __syncthreads();
    float r = sm[0];
    __syncthreads();
    return r;
}

// ---------------- LayerNorm over 384, optional window-partition gather ----------------
// mode: 0 identity, 1 partition (no shift), 2 partition (shift)
__global__ void ln384_kernel(const float* __restrict__ src, float* __restrict__ dst,
                             const float* __restrict__ g, const float* __restrict__ b,
                             int mode) {
    __shared__ float sm[8];
    int row = blockIdx.x;
    int t = (mode == 0) ? row : map_row(row, mode == 2);
    const float* sp = src + (size_t)t * DIM;
    int tx = threadIdx.x;
    float v0 = sp[tx], v1 = sp[tx + 128], v2 = sp[tx + 256];
    float m = block_sum(v0 + v1 + v2, sm) * (1.f / 384.f);
    float d0 = v0 - m, d1 = v1 - m, d2 = v2 - m;
    float var = block_sum(d0 * d0 + d1 * d1 + d2 * d2, sm) * (1.f / 384.f);
    float inv = rsqrtf(var + 1e-5f);
    float* dp = dst + (size_t)row * DIM;
    dp[tx]       = d0 * inv * g[tx]       + b[tx];
    dp[tx + 128] = d1 * inv * g[tx + 128] + b[tx + 128];
    dp[tx + 256] = d2 * inv * g[tx + 256] + b[tx + 256];
}

// ---------------- generic SGEMM  C = A[M,K] @ W[K,Nc] + bias ----------------
// epilogue: 0 store, 1 GELU+store, 2 window-reverse scatter + residual add, 3 residual add
// BM=BN=64, BK=16, 256 threads, 4x4 per thread. All dims divide tiles exactly.
__global__ void gemm_kernel(const float* __restrict__ A, const float* __restrict__ W,
                            const float* __restrict__ bias, float* __restrict__ C,
                            int M, int K, int Nc, int epilogue, int shifted) {
    __shared__ float As[16][64];
    __shared__ float Bs[16][64];
    int t = threadIdx.x;
    int tc = t & 15, tr = t >> 4;
    int rowBase = blockIdx.y * 64;
    int colBase = blockIdx.x * 64;
    float acc[4][4] = {};

    int r_a = t >> 2, kq = t & 3;      // A loader: 64 rows x 4 float4
    int kk  = t >> 4, cq = t & 15;     // B loader: 16 rows x 16 float4
    const float* Aptr = A + (size_t)(rowBase + r_a) * K + kq * 4;
    const float* Wptr = W + (size_t)kk * Nc + colBase + cq * 4;

    for (int kt = 0; kt < K; kt += 16) {
        float4 av = *reinterpret_cast<const float4*>(Aptr + kt);
        float4 bv = *reinterpret_cast<const float4*>(Wptr + (size_t)kt * Nc);
        As[kq * 4 + 0][r_a] = av.x;
        As[kq * 4 + 1][r_a] = av.y;
        As[kq * 4 + 2][r_a] = av.z;
        As[kq * 4 + 3][r_a] = av.w;
        *reinterpret_cast<float4*>(&Bs[kk][cq * 4]) = bv;
        __syncthreads();
        #pragma unroll
        for (int k = 0; k < 16; k++) {
            float4 a4 = *reinterpret_cast<const float4*>(&As[k][tr * 4]);
            float4 b4 = *reinterpret_cast<const float4*>(&Bs[k][tc * 4]);
            float aa[4] = {a4.x, a4.y, a4.z, a4.w};
            float bb[4] = {b4.x, b4.y, b4.z, b4.w};
            #pragma unroll
            for (int i = 0; i < 4; i++)
                #pragma unroll
                for (int j = 0; j < 4; j++) acc[i][j] += aa[i] * bb[j];
        }
        __syncthreads();
    }

    int baseR[4];
    #pragma unroll
    for (int i = 0; i < 4; i++) {
        int gr = rowBase + tr * 4 + i;
        baseR[i] = (epilogue == 2) ? map_row(gr, shifted) : gr;
    }
    #pragma unroll
    for (int i = 0; i < 4; i++) {
        size_t ro = (size_t)baseR[i] * Nc;
        #pragma unroll
        for (int j = 0; j < 4; j++) {
            int gc = colBase + tc * 4 + j;
            float v = acc[i][j] + (bias ? bias[gc] : 0.f);
            if (epilogue == 1) v = 0.5f * v * (1.f + erff(v * 0.7071067811865476f));
            if (epilogue >= 2) v += C[ro + gc];
            C[ro + gc] = v;
        }
    }
}

// ---------------- windowed attention: one block per (window, head) ----------------
__global__ void attn_kernel(const float* __restrict__ qkv, float* __restrict__ o,
                            const float* __restrict__ rpb, int shifted) {
    __shared__ float ksm[49][32];
    __shared__ float vsm[49][32];
    __shared__ float ssm[49][50];
    int head = blockIdx.x % 12;
    int win  = blockIdx.x / 12;
    int wi = win & 63;
    int wh = wi >> 3, ww = wi & 7;
    int base = win * 49;
    int tid = threadIdx.x;

    for (int idx = tid; idx < 49 * 32; idx += 64) {
        int j = idx >> 5, d = idx & 31;
        size_t ro = (size_t)(base + j) * QKVD + head * 32 + d;
        ksm[j][d] = qkv[ro + 384];
        vsm[j][d] = qkv[ro + 768];
    }
    __syncthreads();

    if (tid < 49) {
        int i = tid, ri = i / 7, ci = i % 7;
        float q[32];
        const float* qp = qkv + (size_t)(base + i) * QKVD + head * 32;
        #pragma unroll
        for (int d = 0; d < 32; d++) q[d] = qp[d] * 0.17677669529663687f;

        int lab_i = 0;
        if (shifted) {
            int hh = wh * 7 + ri, wc = ww * 7 + ci;
            int gh = hh < 49 ? 0 : (hh < 53 ? 1 : 2);
            int gw = wc < 49 ? 0 : (wc < 53 ? 1 : 2);
            lab_i = gh * 3 + gw;
        }
        float mx = -1e30f;
        for (int j = 0; j < 49; j++) {
            float s = 0.f;
            #pragma unroll
            for (int d = 0; d < 32; d++) s += q[d] * ksm[j][d];
            int rj = j / 7, cj = j % 7;
            int rpi = (ri - rj + 6) * 13 + (ci - cj + 6);
            s += rpb[rpi * 12 + head];
            if (shifted) {
                int hh = wh * 7 + rj, wc = ww * 7 + cj;
                int gh = hh < 49 ? 0 : (hh < 53 ? 1 : 2);
                int gw = wc < 49 ? 0 : (wc < 53 ? 1 : 2);
                if (gh * 3 + gw != lab_i) s -= 100.0f;
            }
            ssm[i][j] = s;
            mx = fmaxf(mx, s);
        }
        float sum = 0.f;
        for (int j = 0; j < 49; j++) {
            float e = expf(ssm[i][j] - mx);
            ssm[i][j] = e;
            sum += e;
        }
        float inv = 1.0f / sum;
        float accv[32];
        #pragma unroll
        for (int d = 0; d < 32; d++) accv[d] = 0.f;
        for (int j = 0; j < 49; j++) {
            float p = ssm[i][j] * inv;
            #pragma unroll
            for (int d = 0; d < 32; d++) accv[d] += p * vsm[j][d];
        }
        float* op = o + (size_t)(base + i) * DIM + head * 32;
        #pragma unroll
        for (int d = 0; d < 32; d++) op[d] = accv[d];
    }
}

// ---------------- PatchExpand pixel-shuffle + LN over 192 ----------------
__global__ void expand_ln_kernel(const float* __restrict__ e, float* __restrict__ out,
                                 const float* __restrict__ g, const float* __restrict__ b) {
    __shared__ float sm[8];
    int tt = blockIdx.x;                 // output token in [0, B*4L)
    int bb = tt / 12544;
    int rem = tt % 12544;
    int oh = rem / 112, ow = rem % 112;
    int h = oh >> 1, p = oh & 1, w = ow >> 1, q = ow & 1;
    int erow = bb * 3136 + h * 56 + w;
    const float* sp = e + (size_t)erow * EXPD + (p * 2 + q) * 192;
    int tx = threadIdx.x;                // 64 threads, 3 elems each
    float v0 = sp[tx], v1 = sp[tx + 64], v2 = sp[tx + 128];
    float m = block_sum(v0 + v1 + v2, sm) * (1.f / 192.f);
    float d0 = v0 - m, d1 = v1 - m, d2 = v2 - m;
    float var = block_sum(d0 * d0 + d1 * d1 + d2 * d2, sm) * (1.f / 192.f);
    float inv = rsqrtf(var + 1e-5f);
    float* dp = out + (size_t)tt * 192;
    dp[tx]       = d0 * inv * g[tx]       + b[tx];
    dp[tx + 64]  = d1 * inv * g[tx + 64]  + b[tx + 64];
    dp[tx + 128] = d2 * inv * g[tx + 128] + b[tx + 128];
}

__global__ void copy_kernel(float4* __restrict__ dst, const float4* __restrict__ src, int n) {
    int i = blockIdx.x * blockDim.x + threadIdx.x;
    if (i < n) dst[i] = src[i];
}

// ---------------- host orchestration ----------------
extern "C" void kernel_launch(void* const* d_in, const int* in_sizes, int n_in,
                              void* d_out, int out_size) {
    const float* x    = (const float*)d_in[0];
    const float* n1g  = (const float*)d_in[1];
    const float* n1b  = (const float*)d_in[2];
    const float* qkvw = (const float*)d_in[3];
    const float* qkvb = (const float*)d_in[4];
    const float* rpb  = (const float*)d_in[5];
    const float* pw   = (const float*)d_in[6];
    const float* pb   = (const float*)d_in[7];
    const float* n2g  = (const float*)d_in[8];
    const float* n2b  = (const float*)d_in[9];
    const float* f1w  = (const float*)d_in[10];
    const float* f1b  = (const float*)d_in[11];
    const float* f2w  = (const float*)d_in[12];
    const float* f2b  = (const float*)d_in[13];
    const float* ew   = (const float*)d_in[14];
    const float* eg   = (const float*)d_in[15];
    const float* ebv  = (const float*)d_in[16];

    float *xb, *yb, *ob, *bigb;
    cudaGetSymbolAddress((void**)&xb,   g_x);
    cudaGetSymbolAddress((void**)&yb,   g_y);
    cudaGetSymbolAddress((void**)&ob,   g_o);
    cudaGetSymbolAddress((void**)&bigb, g_big);

    // working copy of x (residual stream)
    copy_kernel<<<18816, 256>>>((float4*)xb, (const float4*)x, TOK * DIM / 4);

    const int MB = TOK / 64;   // 784 row tiles
    for (int i = 0; i < 2; i++) {
        int sh = i;  // block 1 is shifted
        // LN1 + window partition (+shift)
        ln384_kernel<<<TOK, 128>>>(xb, yb, n1g + i * DIM, n1b + i * DIM, sh ? 2 : 1);
        // QKV
        gemm_kernel<<<dim3(QKVD / 64, MB), 256>>>(yb, qkvw + (size_t)i * DIM * QKVD,
                                                  qkvb + i * QKVD, bigb,
                                                  TOK, DIM, QKVD, 0, 0);
        // attention per (window, head)
        attn_kernel<<<1024 * 12, 64>>>(bigb, ob, rpb + i * 169 * 12, sh);
        // proj + window reverse (+unshift) + residual into x
        gemm_kernel<<<dim3(DIM / 64, MB), 256>>>(ob, pw + (size_t)i * DIM * DIM,
                                                 pb + i * DIM, xb,
                                                 TOK, DIM, DIM, 2, sh);
        // LN2
        ln384_kernel<<<TOK, 128>>>(xb, yb, n2g + i * DIM, n2b + i * DIM, 0);
        // fc1 + exact GELU
        gemm_kernel<<<dim3(FFN / 64, MB), 256>>>(yb, f1w + (size_t)i * DIM * FFN,
                                                 f1b + i * FFN, bigb,
                                                 TOK, DIM, FFN, 1, 0);
        // fc2 + residual into x
        gemm_kernel<<<dim3(DIM / 64, MB), 256>>>(bigb, f2w + (size_t)i * FFN * DIM,
                                                 f2b + i * DIM, xb,
                                                 TOK, FFN, DIM, 3, 0);
    }

    // PatchExpand GEMM (no bias)
    gemm_kernel<<<dim3(EXPD / 64, MB), 256>>>(xb, ew, nullptr, bigb,
                                              TOK, DIM, EXPD, 0, 0);
    // pixel shuffle + final LN over 192 -> d_out
    expand_ln_kernel<<<TOK * 4, 64>>>(bigb, (float*)d_out, eg, ebv);
}

// round 2
// speedup vs baseline: 1.5537x; 1.5537x over previous
#include <cuda_runtime.h>
#include <math.h>
#include <mma.h>
using namespace nvcuda;

// ---------------- problem constants ----------------
#define TOK   50176
#define DIM   384
#define QKVD  1152
#define FFN   1536
#define EXPD  768

// ---------------- scratch ----------------
static __device__ float g_x  [TOK * DIM];
static __device__ float g_y  [TOK * DIM];
static __device__ float g_o  [TOK * DIM];
static __device__ float g_big[TOK * FFN];

__device__ __forceinline__ int map_row(int ridx, int shifted) {
    int n  = ridx % 49;
    int wi = (ridx / 49) & 63;
    int b  = ridx / (49 * 64);
    int r = n / 7, c = n % 7;
    int wh = wi >> 3, ww = wi & 7;
    int h = wh * 7 + r, w = ww * 7 + c;
    if (shifted) { h = (h + 3) % 56; w = (w + 3) % 56; }
    return b * 3136 + h * 56 + w;
}

__device__ __forceinline__ float block_sum(float v, float* sm) {
    #pragma unroll
    for (int o = 16; o; o >>= 1) v += __shfl_xor_sync(0xffffffffu, v, o);
    int w = threadIdx.x >> 5;
    if ((threadIdx.x & 31) == 0) sm[w] = v;
    __syncthreads();
    if (threadIdx.x < 32) {
        float u = (threadIdx.x < (blockDim.x >> 5)) ? sm[threadIdx.x] : 0.f;
        #pragma unroll
        for (int o = 16; o; o >>= 1) u += __shfl_xor_sync(0xffffffffu, u, o);
        if (threadIdx.x == 0) sm[0] = u;
    }
    __syncthreads();
    float r = sm[0];
    __syncthreads();
    return r;
}

// ---------------- LayerNorm over 384 ----------------
__global__ void ln384_kernel(const float* __restrict__ src, float* __restrict__ dst,
                             const float* __restrict__ g, const float* __restrict__ b,
                             int mode) {
    __shared__ float sm[8];
    int row = blockIdx.x;
    int t = (mode == 0) ? row : map_row(row, mode == 2);
    const float* sp = src + (size_t)t * DIM;
    int tx = threadIdx.x;
    float v0 = sp[tx], v1 = sp[tx + 128], v2 = sp[tx + 256];
    float m = block_sum(v0 + v1 + v2, sm) * (1.f / 384.f);
    float d0 = v0 - m, d1 = v1 - m, d2 = v2 - m;
    float var = block_sum(d0 * d0 + d1 * d1 + d2 * d2, sm) * (1.f / 384.f);
    float inv = rsqrtf(var + 1e-5f);
    float* dp = dst + (size_t)row * DIM;
    dp[tx]       = d0 * inv * g[tx]       + b[tx];
    dp[tx + 128] = d1 * inv * g[tx + 128] + b[tx + 128];
    dp[tx + 256] = d2 * inv * g[tx + 256] + b[tx + 256];
}

// ---------------- TF32 tensor-core GEMM  C = A[M,K] @ W[K,Nc] + bias ----------------
// Tile 128x128x16, 8 warps (4x2), each warp 32x64 (2x4 wmma 16x16x8 frags).
// epilogue: 0 store, 1 GELU+store, 2 window-reverse scatter + residual, 3 residual
#define AS_STR 20
#define BS_STR 136
#define OS_STR 132

__global__ __launch_bounds__(256)
void gemm_tf32_kernel(const float* __restrict__ A, const float* __restrict__ W,
                      const float* __restrict__ bias, float* __restrict__ C,
                      int M, int K, int Nc, int epilogue, int shifted) {
    extern __shared__ float smem[];
    float* As0 = smem;
    float* As1 = As0 + 128 * AS_STR;
    float* Bs0 = As1 + 128 * AS_STR;
    float* Bs1 = Bs0 + 16 * BS_STR;
    float* Asb[2] = {As0, As1};
    float* Bsb[2] = {Bs0, Bs1};
    float* outS = smem;   // alias, used after all MMA work

    int tid = threadIdx.x;
    int wid = tid >> 5;
    int wm = (wid & 3) * 32;       // warp row offset
    int wn = (wid >> 2) * 64;      // warp col offset

    int rowBase = blockIdx.y * 128;
    int colBase = blockIdx.x * 128;

    wmma::fragment<wmma::accumulator, 16, 16, 8, float> acc[2][4];
    #pragma unroll
    for (int i = 0; i < 2; i++)
        #pragma unroll
        for (int j = 0; j < 4; j++) wmma::fill_fragment(acc[i][j], 0.f);

    const float* Ab = A + (size_t)rowBase * K;
    const float* Wb = W + colBase;

    float4 ra[2], rb[2];

    // prologue: load k-tile 0
    #pragma unroll
    for (int l = 0; l < 2; l++) {
        int f = tid + l * 256;
        ra[l] = *reinterpret_cast<const float4*>(Ab + (size_t)(f >> 2) * K + (f & 3) * 4);
        rb[l] = *reinterpret_cast<const float4*>(Wb + (size_t)(f >> 5) * Nc + (f & 31) * 4);
    }
    #pragma unroll
    for (int l = 0; l < 2; l++) {
        int f = tid + l * 256;
        *reinterpret_cast<float4*>(Asb[0] + (f >> 2) * AS_STR + (f & 3) * 4) = ra[l];
        *reinterpret_cast<float4*>(Bsb[0] + (f >> 5) * BS_STR + (f & 31) * 4) = rb[l];
    }
    __syncthreads();

    int nk = K >> 4;
    for (int kt = 0; kt < nk; kt++) {
        int cur = kt & 1;
        if (kt + 1 < nk) {
            int kg = (kt + 1) << 4;
            #pragma unroll
            for (int l = 0; l < 2; l++) {
                int f = tid + l * 256;
                ra[l] = *reinterpret_cast<const float4*>(Ab + (size_t)(f >> 2) * K + kg + (f & 3) * 4);
                rb[l] = *reinterpret_cast<const float4*>(Wb + (size_t)(kg + (f >> 5)) * Nc + (f & 31) * 4);
            }
        }
        #pragma unroll
        for (int k8 = 0; k8 < 2; k8++) {
            wmma::fragment<wmma::matrix_a, 16, 16, 8, wmma::precision::tf32, wmma::row_major> af[2];
            wmma::fragment<wmma::matrix_b, 16, 16, 8, wmma::precision::tf32, wmma::row_major> bf[4];
            #pragma unroll
            for (int i = 0; i < 2; i++) {
                wmma::load_matrix_sync(af[i], Asb[cur] + (wm + i * 16) * AS_STR + k8 * 8, AS_STR);
                #pragma unroll
                for (int e = 0; e < af[i].num_elements; e++)
                    af[i].x[e] = wmma::__float_to_tf32(af[i].x[e]);
            }
            #pragma unroll
            for (int j = 0; j < 4; j++) {
                wmma::load_matrix_sync(bf[j], Bsb[cur] + (k8 * 8) * BS_STR + wn + j * 16, BS_STR);
                #pragma unroll
                for (int e = 0; e < bf[j].num_elements; e++)
                    bf[j].x[e] = wmma::__float_to_tf32(bf[j].x[e]);
            }
            #pragma unroll
            for (int i = 0; i < 2; i++)
                #pragma unroll
                for (int j = 0; j < 4; j++)
                    wmma::mma_sync(acc[i][j], af[i], bf[j], acc[i][j]);
        }
        if (kt + 1 < nk) {
            int nxt = cur ^ 1;
            #pragma unroll
            for (int l = 0; l < 2; l++) {
                int f = tid + l * 256;
                *reinterpret_cast<float4*>(Asb[nxt] + (f >> 2) * AS_STR + (f & 3) * 4) = ra[l];
                *reinterpret_cast<float4*>(Bsb[nxt] + (f >> 5) * BS_STR + (f & 31) * 4) = rb[l];
            }
        }
        __syncthreads();
    }

    // epilogue: stage accumulators in smem (aliases load buffers — all MMA done)
    #pragma unroll
    for (int i = 0; i < 2; i++)
        #pragma unroll
        for (int j = 0; j < 4; j++)
            wmma::store_matrix_sync(outS + (wm + i * 16) * OS_STR + wn + j * 16,
                                    acc[i][j], OS_STR, wmma::mem_row_major);
    __syncthreads();

    #pragma unroll 4
    for (int e = 0; e < 64; e++) {
        int idx = tid + e * 256;
        int r = idx >> 7, c = idx & 127;
        int gr = rowBase + r, gc = colBase + c;
        float v = outS[r * OS_STR + c] + (bias ? bias[gc] : 0.f);
        if (epilogue == 1) v = 0.5f * v * (1.f + erff(v * 0.7071067811865476f));
        int orow = (epilogue == 2) ? map_row(gr, shifted) : gr;
        size_t off = (size_t)orow * Nc + gc;
        if (epilogue >= 2) v += C[off];
        C[off] = v;
    }
}

// ---------------- windowed attention: one block per (window, head) ----------------
__global__ void attn_kernel(const float* __restrict__ qkv, float* __restrict__ o,
                            const float* __restrict__ rpb, int shifted) {
    __shared__ float ksm[49][32];
    __shared__ float vsm[49][32];
    __shared__ float ssm[49][50];
    int head = blockIdx.x % 12;
    int win  = blockIdx.x / 12;
    int wi = win & 63;
    int wh = wi >> 3, ww = wi & 7;
    int base = win * 49;
    int tid = threadIdx.x;

    for (int idx = tid; idx < 49 * 32; idx += 64) {
        int j = idx >> 5, d = idx & 31;
        size_t ro = (size_t)(base + j) * QKVD + head * 32 + d;
        ksm[j][d] = qkv[ro + 384];
        vsm[j][d] = qkv[ro + 768];
    }
    __syncthreads();

    if (tid < 49) {
        int i = tid, ri = i / 7, ci = i % 7;
        float q[32];
        const float* qp = qkv + (size_t)(base + i) * QKVD + head * 32;
        #pragma unroll
        for (int d = 0; d < 32; d++) q[d] = qp[d] * 0.17677669529663687f;

        int lab_i = 0;
        if (shifted) {
            int hh = wh * 7 + ri, wc = ww * 7 + ci;
            int gh = hh < 49 ? 0 : (hh < 53 ? 1 : 2);
            int gw = wc < 49 ? 0 : (wc < 53 ? 1 : 2);
            lab_i = gh * 3 + gw;
        }
        float mx = -1e30f;
        for (int j = 0; j < 49; j++) {
            float s = 0.f;
            #pragma unroll
            for (int d = 0; d < 32; d++) s += q[d] * ksm[j][d];
            int rj = j / 7, cj = j % 7;
            int rpi = (ri - rj + 6) * 13 + (ci - cj + 6);
            s += rpb[rpi * 12 + head];
            if (shifted) {
                int hh = wh * 7 + rj, wc = ww * 7 + cj;
                int gh = hh < 49 ? 0 : (hh < 53 ? 1 : 2);
                int gw = wc < 49 ? 0 : (wc < 53 ? 1 : 2);
                if (gh * 3 + gw != lab_i) s -= 100.0f;
            }
            ssm[i][j] = s;
            mx = fmaxf(mx, s);
        }
        float sum = 0.f;
        for (int j = 0; j < 49; j++) {
            float e = expf(ssm[i][j] - mx);
            ssm[i][j] = e;
            sum += e;
        }
        float inv = 1.0f / sum;
        float accv[32];
        #pragma unroll
        for (int d = 0; d < 32; d++) accv[d] = 0.f;
        for (int j = 0; j < 49; j++) {
            float p = ssm[i][j] * inv;
            #pragma unroll
            for (int d = 0; d < 32; d++) accv[d] += p * vsm[j][d];
        }
        float* op = o + (size_t)(base + i) * DIM + head * 32;
        #pragma unroll
        for (int d = 0; d < 32; d++) op[d] = accv[d];
    }
}

// ---------------- PatchExpand pixel-shuffle + LN over 192 ----------------
__global__ void expand_ln_kernel(const float* __restrict__ e, float* __restrict__ out,
                                 const float* __restrict__ g, const float* __restrict__ b) {
    __shared__ float sm[8];
    int tt = blockIdx.x;
    int bb = tt / 12544;
    int rem = tt % 12544;
    int oh = rem / 112, ow = rem % 112;
    int h = oh >> 1, p = oh & 1, w = ow >> 1, q = ow & 1;
    int erow = bb * 3136 + h * 56 + w;
    const float* sp = e + (size_t)erow * EXPD + (p * 2 + q) * 192;
    int tx = threadIdx.x;
    float v0 = sp[tx], v1 = sp[tx + 64], v2 = sp[tx + 128];
    float m = block_sum(v0 + v1 + v2, sm) * (1.f / 192.f);
    float d0 = v0 - m, d1 = v1 - m, d2 = v2 - m;
    float var = block_sum(d0 * d0 + d1 * d1 + d2 * d2, sm) * (1.f / 192.f);
    float inv = rsqrtf(var + 1e-5f);
    float* dp = out + (size_t)tt * 192;
    dp[tx]       = d0 * inv * g[tx]       + b[tx];
    dp[tx + 64]  = d1 * inv * g[tx + 64]  + b[tx + 64];
    dp[tx + 128] = d2 * inv * g[tx + 128] + b[tx + 128];
}

__global__ void copy_kernel(float4* __restrict__ dst, const float4* __restrict__ src, int n) {
    int i = blockIdx.x * blockDim.x + threadIdx.x;
    if (i < n) dst[i] = src[i];
}

// ---------------- host orchestration ----------------
extern "C" void kernel_launch(void* const* d_in, const int* in_sizes, int n_in,
                              void* d_out, int out_size) {
    const float* x    = (const float*)d_in[0];
    const float* n1g  = (const float*)d_in[1];
    const float* n1b  = (const float*)d_in[2];
    const float* qkvw = (const float*)d_in[3];
    const float* qkvb = (const float*)d_in[4];
    const float* rpb  = (const float*)d_in[5];
    const float* pw   = (const float*)d_in[6];
    const float* pb   = (const float*)d_in[7];
    const float* n2g  = (const float*)d_in[8];
    const float* n2b  = (const float*)d_in[9];
    const float* f1w  = (const float*)d_in[10];
    const float* f1b  = (const float*)d_in[11];
    const float* f2w  = (const float*)d_in[12];
    const float* f2b  = (const float*)d_in[13];
    const float* ew   = (const float*)d_in[14];
    const float* eg   = (const float*)d_in[15];
    const float* ebv  = (const float*)d_in[16];

    float *xb, *yb, *ob, *bigb;
    cudaGetSymbolAddress((void**)&xb,   g_x);
    cudaGetSymbolAddress((void**)&yb,   g_y);
    cudaGetSymbolAddress((void**)&ob,   g_o);
    cudaGetSymbolAddress((void**)&bigb, g_big);

    static int smem_set = 0;
    const int GEMM_SMEM = 128 * OS_STR * sizeof(float);  // 67584 B (covers load bufs too)
    if (!smem_set) {
        cudaFuncSetAttribute(gemm_tf32_kernel,
                             cudaFuncAttributeMaxDynamicSharedMemorySize, GEMM_SMEM);
        smem_set = 1;
    }

    copy_kernel<<<18816, 256>>>((float4*)xb, (const float4*)x, TOK * DIM / 4);

    const int MB = TOK / 128;   // 392 row tiles
    for (int i = 0; i < 2; i++) {
        int sh = i;
        ln384_kernel<<<TOK, 128>>>(xb, yb, n1g + i * DIM, n1b + i * DIM, sh ? 2 : 1);
        gemm_tf32_kernel<<<dim3(QKVD / 128, MB), 256, GEMM_SMEM>>>(
            yb, qkvw + (size_t)i * DIM * QKVD, qkvb + i * QKVD, bigb,
            TOK, DIM, QKVD, 0, 0);
        attn_kernel<<<1024 * 12, 64>>>(bigb, ob, rpb + i * 169 * 12, sh);
        gemm_tf32_kernel<<<dim3(DIM / 128, MB), 256, GEMM_SMEM>>>(
            ob, pw + (size_t)i * DIM * DIM, pb + i * DIM, xb,
            TOK, DIM, DIM, 2, sh);
        ln384_kernel<<<TOK, 128>>>(xb, yb, n2g + i * DIM, n2b + i * DIM, 0);
        gemm_tf32_kernel<<<dim3(FFN / 128, MB), 256, GEMM_SMEM>>>(
            yb, f1w + (size_t)i * DIM * FFN, f1b + i * FFN, bigb,
            TOK, DIM, FFN, 1, 0);
        gemm_tf32_kernel<<<dim3(DIM / 128, MB), 256, GEMM_SMEM>>>(
            bigb, f2w + (size_t)i * FFN * DIM, f2b + i * DIM, xb,
            TOK, FFN, DIM, 3, 0);
    }

    gemm_tf32_kernel<<<dim3(EXPD / 128, MB), 256, GEMM_SMEM>>>(
        xb, ew, nullptr, bigb, TOK, DIM, EXPD, 0, 0);
    expand_ln_kernel<<<TOK * 4, 64>>>(bigb, (float*)d_out, eg, ebv);
}

// round 4
// speedup vs baseline: 1.7268x; 1.1114x over previous
#include <cuda_runtime.h>
#include <math.h>
#include <stdint.h>
#include <mma.h>
using namespace nvcuda;

// ---------------- problem constants ----------------
#define TOK   50176
#define DIM   384
#define QKVD  1152
#define FFN   1536
#define EXPD  768

// ---------------- scratch ----------------
static __device__ float g_x  [TOK * DIM];
static __device__ float g_y  [TOK * DIM];
static __device__ float g_o  [TOK * DIM];
static __device__ float g_big[TOK * FFN];
static __device__ float g_w  [3833856];     // tf32-rounded weights (original [K,N] layout)

#define W_QKV 0
#define W_PROJ 884736
#define W_FC1 1179648
#define W_FC2 2359296
#define W_EXP 3538944

// ---------------- helpers ----------------
__device__ __forceinline__ uint32_t smem_u32(const void* p) {
    uint32_t a;
    asm("{ .reg .u64 t; cvta.to.shared.u64 t, %1; cvt.u32.u64 %0, t; }" : "=r"(a) : "l"(p));
    return a;
}
__device__ __forceinline__ float to_tf32(float x) {
    float r; asm("cvt.rna.tf32.f32 %0, %1;" : "=f"(r) : "f"(x)); return r;
}
__device__ __forceinline__ void cp16(uint32_t s, const void* g) {
    asm volatile("cp.async.cg.shared.global [%0], [%1], 16;" :: "r"(s), "l"(g) : "memory");
}
#define CP_COMMIT() asm volatile("cp.async.commit_group;" ::: "memory")
#define CP_WAIT(n)  asm volatile("cp.async.wait_group %0;" :: "n"(n) : "memory")

__device__ __forceinline__ int map_row(int ridx, int shifted) {
    int n  = ridx % 49;
    int wi = (ridx / 49) & 63;
    int b  = ridx / (49 * 64);
    int r = n / 7, c = n % 7;
    int wh = wi >> 3, ww = wi & 7;
    int h = wh * 7 + r, w = ww * 7 + c;
    if (shifted) { h = (h + 3) % 56; w = (w + 3) % 56; }
    return b * 3136 + h * 56 + w;
}

// ---------------- tf32 wmma GEMM, cp.async 3-stage, BK=32 ----------------
// C = A[M,K] @ W[K,Nc] + bias.  CTA tile 128x128, 8 warps (4x2), warp 32x64.
// A and W must already be tf32-rounded.
// epilogue: 0 store, 1 GELU(round)+store, 2 scatter+residual, 3 residual (+ rounded mirror)
#define ASTR 36
#define BSTR 132
#define A_STAGE (128 * ASTR)
#define B_STAGE (32 * BSTR)
#define STG (A_STAGE + B_STAGE)     // 8832 floats / stage
#define OSTR 132

__global__ __launch_bounds__(256, 2)
void gemm_tc(const float* __restrict__ A, const float* __restrict__ W,
             const float* __restrict__ bias, float* __restrict__ C,
             float* __restrict__ mirror,
             int K, int Nc, int epilogue, int shifted) {
    extern __shared__ float sm[];
    int tid = threadIdx.x;
    int wid = tid >> 5;
    int wm = (wid & 3) * 32;
    int wn = (wid >> 2) * 64;
    int rowBase = blockIdx.y * 128;
    int colBase = blockIdx.x * 128;
    int nk = K >> 5;

    wmma::fragment<wmma::accumulator, 16, 16, 8, float> acc[2][4];
    #pragma unroll
    for (int i = 0; i < 2; i++)
        #pragma unroll
        for (int j = 0; j < 4; j++) wmma::fill_fragment(acc[i][j], 0.f);

    // per-thread load slots (8 x 16B per stage)
    int rA = (tid * 4 + 0) ? 0 : 0; // dummy to keep compiler quiet
    int ar = tid >> 1, aq = (tid & 1) * 16;           // unused alt mapping
    (void)rA; (void)ar; (void)aq;

    #define STAGE_LOAD(kt, buf) do {                                              \
        float* As_ = sm + (buf) * STG;                                            \
        float* Bs_ = As_ + A_STAGE;                                               \
        uint32_t as_ = smem_u32(As_), bs_ = smem_u32(Bs_);                        \
        int kg_ = (kt) * 32;                                                      \
        _Pragma("unroll")                                                         \
        for (int l = 0; l < 4; l++) {                                             \
            int c = tid + l * 256;                                                \
            int r = c >> 3, q = (c & 7) * 4;                                      \
            cp16(as_ + (uint32_t)(r * ASTR + q) * 4,                              \
                 A + (size_t)(rowBase + r) * K + kg_ + q);                        \
            int kr = c >> 5, nq = (c & 31) * 4;                                   \
            cp16(bs_ + (uint32_t)(kr * BSTR + nq) * 4,                            \
                 W + (size_t)(kg_ + kr) * Nc + colBase + nq);                     \
        }                                                                         \
    } while (0)

    STAGE_LOAD(0, 0); CP_COMMIT();
    STAGE_LOAD(1, 1); CP_COMMIT();

    for (int kt = 0; kt < nk; kt++) {
        if (kt + 2 < nk) { STAGE_LOAD(kt + 2, (kt + 2) % 3); CP_COMMIT(); CP_WAIT(2); }
        else if (kt + 1 < nk) { CP_WAIT(1); }
        else { CP_WAIT(0); }
        __syncthreads();

        const float* As = sm + (kt % 3) * STG;
        const float* Bs = As + A_STAGE;
        #pragma unroll
        for (int k8 = 0; k8 < 4; k8++) {
            wmma::fragment<wmma::matrix_a, 16, 16, 8, wmma::precision::tf32, wmma::row_major> af[2];
            wmma::fragment<wmma::matrix_b, 16, 16, 8, wmma::precision::tf32, wmma::row_major> bf[4];
            #pragma unroll
            for (int i = 0; i < 2; i++)
                wmma::load_matrix_sync(af[i], As + (wm + i * 16) * ASTR + k8 * 8, ASTR);
            #pragma unroll
            for (int j = 0; j < 4; j++)
                wmma::load_matrix_sync(bf[j], Bs + (k8 * 8) * BSTR + wn + j * 16, BSTR);
            #pragma unroll
            for (int i = 0; i < 2; i++)
                #pragma unroll
                for (int j = 0; j < 4; j++)
                    wmma::mma_sync(acc[i][j], af[i], bf[j], acc[i][j]);
        }
        __syncthreads();
    }

    // epilogue: stage accumulators to smem (reuses pipeline buffers)
    #pragma unroll
    for (int i = 0; i < 2; i++)
        #pragma unroll
        for (int j = 0; j < 4; j++)
            wmma::store_matrix_sync(sm + (wm + i * 16) * OSTR + wn + j * 16,
                                    acc[i][j], OSTR, wmma::mem_row_major);
    __syncthreads();

    #pragma unroll 4
    for (int e = 0; e < 64; e++) {
        int idx = tid + e * 256;
        int r = idx >> 7, c = idx & 127;
        int gr = rowBase + r, gc = colBase + c;
        float v = sm[r * OSTR + c] + (bias ? bias[gc] : 0.f);
        if (epilogue == 1) v = to_tf32(0.5f * v * (1.f + erff(v * 0.7071067811865476f)));
        int orow = (epilogue == 2) ? map_row(gr, shifted) : gr;
        size_t off = (size_t)orow * Nc + gc;
        if (epilogue >= 2) v += C[off];
        C[off] = v;
        if (epilogue == 3) mirror[off] = to_tf32(v);
    }
}

// ---------------- weight round-copy (fp32 -> tf32-rounded fp32) ----------------
__global__ void round_kernel(const float4* __restrict__ in, float4* __restrict__ out, int n4) {
    int i = blockIdx.x * blockDim.x + threadIdx.x;
    if (i < n4) {
        float4 v = in[i];
        v.x = to_tf32(v.x); v.y = to_tf32(v.y); v.z = to_tf32(v.z); v.w = to_tf32(v.w);
        out[i] = v;
    }
}

// ---------------- LayerNorm over 384 (outputs tf32-rounded) ----------------
__device__ __forceinline__ float block_sum(float v, float* sm) {
    #pragma unroll
    for (int o = 16; o; o >>= 1) v += __shfl_xor_sync(0xffffffffu, v, o);
    int w = threadIdx.x >> 5;
    if ((threadIdx.x & 31) == 0) sm[w] = v;
    __syncthreads();
    if (threadIdx.x < 32) {
        float u = (threadIdx.x < (blockDim.x >> 5)) ? sm[threadIdx.x] : 0.f;
        #pragma unroll
        for (int o = 16; o; o >>= 1) u += __shfl_xor_sync(0xffffffffu, u, o);
        if (threadIdx.x == 0) sm[0] = u;
    }
    __syncthreads();
    float r = sm[0];
    __syncthreads();
    return r;
}

__global__ void ln384_kernel(const float* __restrict__ src, float* __restrict__ dst,
                             const float* __restrict__ g, const float* __restrict__ b,
                             int mode) {
    __shared__ float sm[8];
    int row = blockIdx.x;
    int t = (mode == 0) ? row : map_row(row, mode == 2);
    const float* sp = src + (size_t)t * DIM;
    int tx = threadIdx.x;
    float v0 = sp[tx], v1 = sp[tx + 128], v2 = sp[tx + 256];
    float m = block_sum(v0 + v1 + v2, sm) * (1.f / 384.f);
    float d0 = v0 - m, d1 = v1 - m, d2 = v2 - m;
    float var = block_sum(d0 * d0 + d1 * d1 + d2 * d2, sm) * (1.f / 384.f);
    float inv = rsqrtf(var + 1e-5f);
    float* dp = dst + (size_t)row * DIM;
    dp[tx]       = to_tf32(d0 * inv * g[tx]       + b[tx]);
    dp[tx + 128] = to_tf32(d1 * inv * g[tx + 128] + b[tx + 128]);
    dp[tx + 256] = to_tf32(d2 * inv * g[tx + 256] + b[tx + 256]);
}

// ---------------- windowed attention: 2 heads per 128-thread block ----------------
__global__ void attn_kernel(const float* __restrict__ qkv, float* __restrict__ o,
                            const float* __restrict__ rpb, int shifted) {
    __shared__ float ksm[2][49][32];
    __shared__ float vsm[2][49][32];
    __shared__ float ssm[2][49][50];
    int pair = blockIdx.x;
    int win  = pair / 6;
    int hp   = (pair % 6) * 2;
    int sub  = threadIdx.x >> 6;
    int t    = threadIdx.x & 63;
    int head = hp + sub;
    int wi = win & 63;
    int wh = wi >> 3, ww = wi & 7;
    int base = win * 49;

    for (int idx = t; idx < 49 * 32; idx += 64) {
        int j = idx >> 5, d = idx & 31;
        size_t ro = (size_t)(base + j) * QKVD + head * 32 + d;
        ksm[sub][j][d] = qkv[ro + 384];
        vsm[sub][j][d] = qkv[ro + 768];
    }
    __syncthreads();

    if (t < 49) {
        int i = t, ri = i / 7, ci = i % 7;
        float q[32];
        const float* qp = qkv + (size_t)(base + i) * QKVD + head * 32;
        #pragma unroll
        for (int d = 0; d < 32; d++) q[d] = qp[d] * 0.17677669529663687f;

        int lab_i = 0;
        if (shifted) {
            int hh = wh * 7 + ri, wc = ww * 7 + ci;
            int gh = hh < 49 ? 0 : (hh < 53 ? 1 : 2);
            int gw = wc < 49 ? 0 : (wc < 53 ? 1 : 2);
            lab_i = gh * 3 + gw;
        }
        float mx = -1e30f;
        for (int j = 0; j < 49; j++) {
            float s = 0.f;
            #pragma unroll
            for (int d = 0; d < 32; d++) s += q[d] * ksm[sub][j][d];
            int rj = j / 7, cj = j % 7;
            int rpi = (ri - rj + 6) * 13 + (ci - cj + 6);
            s += rpb[rpi * 12 + head];
            if (shifted) {
                int hh = wh * 7 + rj, wc = ww * 7 + cj;
                int gh = hh < 49 ? 0 : (hh < 53 ? 1 : 2);
                int gw = wc < 49 ? 0 : (wc < 53 ? 1 : 2);
                if (gh * 3 + gw != lab_i) s -= 100.0f;
            }
            ssm[sub][i][j] = s;
            mx = fmaxf(mx, s);
        }
        float sum = 0.f;
        for (int j = 0; j < 49; j++) {
            float e = expf(ssm[sub][i][j] - mx);
            ssm[sub][i][j] = e;
            sum += e;
        }
        float inv = 1.0f / sum;
        float accv[32];
        #pragma unroll
        for (int d = 0; d < 32; d++) accv[d] = 0.f;
        for (int j = 0; j < 49; j++) {
            float p = ssm[sub][i][j] * inv;
            #pragma unroll
            for (int d = 0; d < 32; d++) accv[d] += p * vsm[sub][j][d];
        }
        float* op = o + (size_t)(base + i) * DIM + head * 32;
        #pragma unroll
        for (int d = 0; d < 32; d++) op[d] = to_tf32(accv[d]);
    }
}

// ---------------- PatchExpand pixel-shuffle + LN over 192 ----------------
__global__ void expand_ln_kernel(const float* __restrict__ e, float* __restrict__ out,
                                 const float* __restrict__ g, const float* __restrict__ b) {
    __shared__ float sm[8];
    int tt = blockIdx.x;
    int bb = tt / 12544;
    int rem = tt % 12544;
    int oh = rem / 112, ow = rem % 112;
    int h = oh >> 1, p = oh & 1, w = ow >> 1, q = ow & 1;
    int erow = bb * 3136 + h * 56 + w;
    const float* sp = e + (size_t)erow * EXPD + (p * 2 + q) * 192;
    int tx = threadIdx.x;
    float v0 = sp[tx], v1 = sp[tx + 64], v2 = sp[tx + 128];
    float m = block_sum(v0 + v1 + v2, sm) * (1.f / 192.f);
    float d0 = v0 - m, d1 = v1 - m, d2 = v2 - m;
    float var = block_sum(d0 * d0 + d1 * d1 + d2 * d2, sm) * (1.f / 192.f);
    float inv = rsqrtf(var + 1e-5f);
    float* dp = out + (size_t)tt * 192;
    dp[tx]       = d0 * inv * g[tx]       + b[tx];
    dp[tx + 64]  = d1 * inv * g[tx + 64]  + b[tx + 64];
    dp[tx + 128] = d2 * inv * g[tx + 128] + b[tx + 128];
}

__global__ void copy_kernel(float4* __restrict__ dst, const float4* __restrict__ src, int n) {
    int i = blockIdx.x * blockDim.x + threadIdx.x;
    if (i < n) dst[i] = src[i];
}

// ---------------- host orchestration ----------------
extern "C" void kernel_launch(void* const* d_in, const int* in_sizes, int n_in,
                              void* d_out, int out_size) {
    const float* x    = (const float*)d_in[0];
    const float* n1g  = (const float*)d_in[1];
    const float* n1b  = (const float*)d_in[2];
    const float* qkvw = (const float*)d_in[3];
    const float* qkvb = (const float*)d_in[4];
    const float* rpb  = (const float*)d_in[5];
    const float* pw   = (const float*)d_in[6];
    const float* pb   = (const float*)d_in[7];
    const float* n2g  = (const float*)d_in[8];
    const float* n2b  = (const float*)d_in[9];
    const float* f1w  = (const float*)d_in[10];
    const float* f1b  = (const float*)d_in[11];
    const float* f2w  = (const float*)d_in[12];
    const float* f2b  = (const float*)d_in[13];
    const float* ew   = (const float*)d_in[14];
    const float* eg   = (const float*)d_in[15];
    const float* ebv  = (const float*)d_in[16];

    float *xb, *yb, *ob, *bigb, *wr;
    cudaGetSymbolAddress((void**)&xb,   g_x);
    cudaGetSymbolAddress((void**)&yb,   g_y);
    cudaGetSymbolAddress((void**)&ob,   g_o);
    cudaGetSymbolAddress((void**)&bigb, g_big);
    cudaGetSymbolAddress((void**)&wr,   g_w);

    static int smem_set = 0;
    const int GEMM_SMEM = 3 * STG * sizeof(float);   // 105984 B
    if (!smem_set) {
        cudaFuncSetAttribute(gemm_tc,
                             cudaFuncAttributeMaxDynamicSharedMemorySize, GEMM_SMEM);
        smem_set = 1;
    }

    // round all weights to tf32 once
    round_kernel<<<(884736/4 + 255)/256, 256>>>((const float4*)qkvw, (float4*)(wr + W_QKV), 884736/4);
    round_kernel<<<(294912/4 + 255)/256, 256>>>((const float4*)pw,   (float4*)(wr + W_PROJ), 294912/4);
    round_kernel<<<(1179648/4 + 255)/256, 256>>>((const float4*)f1w, (float4*)(wr + W_FC1), 1179648/4);
    round_kernel<<<(1179648/4 + 255)/256, 256>>>((const float4*)f2w, (float4*)(wr + W_FC2), 1179648/4);
    round_kernel<<<(294912/4 + 255)/256, 256>>>((const float4*)ew,   (float4*)(wr + W_EXP), 294912/4);

    copy_kernel<<<18816, 256>>>((float4*)xb, (const float4*)x, TOK * DIM / 4);

    const int MB = TOK / 128;   // 392 row tiles
    for (int i = 0; i < 2; i++) {
        int sh = i;
        ln384_kernel<<<TOK, 128>>>(xb, yb, n1g + i * DIM, n1b + i * DIM, sh ? 2 : 1);
        gemm_tc<<<dim3(QKVD / 128, MB), 256, GEMM_SMEM>>>(
            yb, wr + W_QKV + (size_t)i * DIM * QKVD, qkvb + i * QKVD, bigb, nullptr,
            DIM, QKVD, 0, 0);
        attn_kernel<<<1024 * 6, 128>>>(bigb, ob, rpb + i * 169 * 12, sh);
        gemm_tc<<<dim3(DIM / 128, MB), 256, GEMM_SMEM>>>(
            ob, wr + W_PROJ + (size_t)i * DIM * DIM, pb + i * DIM, xb, nullptr,
            DIM, DIM, 2, sh);
        ln384_kernel<<<TOK, 128>>>(xb, yb, n2g + i * DIM, n2b + i * DIM, 0);
        gemm_tc<<<dim3(FFN / 128, MB), 256, GEMM_SMEM>>>(
            yb, wr + W_FC1 + (size_t)i * DIM * FFN, f1b + i * FFN, bigb, nullptr,
            DIM, FFN, 1, 0);
        gemm_tc<<<dim3(DIM / 128, MB), 256, GEMM_SMEM>>>(
            bigb, wr + W_FC2 + (size_t)i * FFN * DIM, f2b + i * DIM, xb, yb,
            FFN, DIM, 3, 0);
    }

    // expand GEMM reads the tf32-rounded mirror of the final residual
    gemm_tc<<<dim3(EXPD / 128, MB), 256, GEMM_SMEM>>>(
        yb, wr + W_EXP, nullptr, bigb, nullptr, DIM, EXPD, 0, 0);
    expand_ln_kernel<<<TOK * 4, 64>>>(bigb, (float*)d_out, eg, ebv);
}

// round 5
// speedup vs baseline: 3.8120x; 2.2076x over previous
#include <cuda_runtime.h>
#include <cuda_fp16.h>
#include <math.h>
#include <stdint.h>
#include <mma.h>
using namespace nvcuda;

// ---------------- problem constants ----------------
#define TOK   50176
#define DIM   384
#define QKVD  1152
#define FFN   1536
#define EXPD  768

// ---------------- scratch ----------------
static __device__ float  g_x  [TOK * DIM];     // fp32 residual stream
static __device__ __half g_xh [TOK * DIM];     // fp16 mirror of final residual
static __device__ __half g_y  [TOK * DIM];     // LN outputs (fp16)
static __device__ __half g_o  [TOK * DIM];     // attention out (fp16)
static __device__ float  g_big[TOK * FFN];     // qkv/mid (as half) or expand out (float)
static __device__ __half g_w  [3833856];       // fp16 weights

#define W_QKV 0
#define W_PROJ 884736
#define W_FC1 1179648
#define W_FC2 2359296
#define W_EXP 3538944

// ---------------- helpers ----------------
__device__ __forceinline__ uint32_t smem_u32(const void* p) {
    uint32_t a;
    asm("{ .reg .u64 t; cvta.to.shared.u64 t, %1; cvt.u32.u64 %0, t; }" : "=r"(a) : "l"(p));
    return a;
}
__device__ __forceinline__ void cp16(uint32_t s, const void* g) {
    asm volatile("cp.async.cg.shared.global [%0], [%1], 16;" :: "r"(s), "l"(g) : "memory");
}
#define CP_COMMIT() asm volatile("cp.async.commit_group;" ::: "memory")
#define CP_WAIT(n)  asm volatile("cp.async.wait_group %0;" :: "n"(n) : "memory")

__device__ __forceinline__ int map_row(int ridx, int shifted) {
    int n  = ridx % 49;
    int wi = (ridx / 49) & 63;
    int b  = ridx / (49 * 64);
    int r = n / 7, c = n % 7;
    int wh = wi >> 3, ww = wi & 7;
    int h = wh * 7 + r, w = ww * 7 + c;
    if (shifted) { h = (h + 3) % 56; w = (w + 3) % 56; }
    return b * 3136 + h * 56 + w;
}

// ---------------- fp16 wmma GEMM, cp.async 3-stage, BK=32 ----------------
// C = A[M,K] @ W[K,Nc] + bias.  CTA tile 128x128, 8 warps (4x2), warp 32x64.
// epilogue: 0 plain (out_half selects dtype), 1 GELU->half, 2 scatter+residual fp32,
//           3 residual fp32 + half mirror
#define ASTR 40
#define BSTR 136
#define A_STAGE (128 * ASTR)            // halves
#define B_STAGE (32 * BSTR)
#define STG (A_STAGE + B_STAGE)         // 9472 halves = 18944 B / stage
#define OSTR 132

__global__ __launch_bounds__(256, 2)
void gemm_fp16(const __half* __restrict__ A, const __half* __restrict__ W,
               const float* __restrict__ bias, void* __restrict__ Cv,
               __half* __restrict__ mirror,
               int K, int Nc, int epilogue, int shifted, int out_half) {
    extern __shared__ __align__(16) char smraw[];
    __half* smh = (__half*)smraw;
    float*  smf = (float*)smraw;
    int tid = threadIdx.x;
    int wid = tid >> 5;
    int wm = (wid & 3) * 32;
    int wn = (wid >> 2) * 64;
    int rowBase = blockIdx.y * 128;
    int colBase = blockIdx.x * 128;
    int nk = K >> 5;

    wmma::fragment<wmma::accumulator, 16, 16, 16, float> acc[2][4];
    #pragma unroll
    for (int i = 0; i < 2; i++)
        #pragma unroll
        for (int j = 0; j < 4; j++) wmma::fill_fragment(acc[i][j], 0.f);

    #define STAGE_LOAD(kt, buf) do {                                              \
        __half* As_ = smh + (buf) * STG;                                          \
        __half* Bs_ = As_ + A_STAGE;                                              \
        uint32_t as_ = smem_u32(As_), bs_ = smem_u32(Bs_);                        \
        int kg_ = (kt) * 32;                                                      \
        _Pragma("unroll")                                                         \
        for (int l = 0; l < 2; l++) {                                             \
            int c = tid + l * 256;                                                \
            int r = c >> 2, q = (c & 3) * 8;                                      \
            cp16(as_ + (uint32_t)(r * ASTR + q) * 2,                              \
                 A + (size_t)(rowBase + r) * K + kg_ + q);                        \
            int kr = c >> 4, nq = (c & 15) * 8;                                   \
            cp16(bs_ + (uint32_t)(kr * BSTR + nq) * 2,                            \
                 W + (size_t)(kg_ + kr) * Nc + colBase + nq);                     \
        }                                                                         \
    } while (0)

    STAGE_LOAD(0, 0); CP_COMMIT();
    STAGE_LOAD(1, 1); CP_COMMIT();

    for (int kt = 0; kt < nk; kt++) {
        if (kt + 2 < nk) { STAGE_LOAD(kt + 2, (kt + 2) % 3); CP_COMMIT(); CP_WAIT(2); }
        else if (kt + 1 < nk) { CP_WAIT(1); }
        else { CP_WAIT(0); }
        __syncthreads();

        const __half* As = smh + (kt % 3) * STG;
        const __half* Bs = As + A_STAGE;
        #pragma unroll
        for (int k16 = 0; k16 < 2; k16++) {
            wmma::fragment<wmma::matrix_a, 16, 16, 16, __half, wmma::row_major> af[2];
            wmma::fragment<wmma::matrix_b, 16, 16, 16, __half, wmma::row_major> bf[4];
            #pragma unroll
            for (int i = 0; i < 2; i++)
                wmma::load_matrix_sync(af[i], As + (wm + i * 16) * ASTR + k16 * 16, ASTR);
            #pragma unroll
            for (int j = 0; j < 4; j++)
                wmma::load_matrix_sync(bf[j], Bs + (k16 * 16) * BSTR + wn + j * 16, BSTR);
            #pragma unroll
            for (int i = 0; i < 2; i++)
                #pragma unroll
                for (int j = 0; j < 4; j++)
                    wmma::mma_sync(acc[i][j], af[i], bf[j], acc[i][j]);
        }
        __syncthreads();
    }

    // stage accumulators to smem as fp32
    #pragma unroll
    for (int i = 0; i < 2; i++)
        #pragma unroll
        for (int j = 0; j < 4; j++)
            wmma::store_matrix_sync(smf + (wm + i * 16) * OSTR + wn + j * 16,
                                    acc[i][j], OSTR, wmma::mem_row_major);
    __syncthreads();

    if (epilogue <= 1) {
        if (out_half) {
            __half* C = (__half*)Cv;
            #pragma unroll 4
            for (int e = 0; e < 32; e++) {
                int idx = tid + e * 256;
                int r = idx >> 6, c2 = (idx & 63) * 2;
                int gc = colBase + c2;
                float v0 = smf[r * OSTR + c2]     + (bias ? bias[gc]     : 0.f);
                float v1 = smf[r * OSTR + c2 + 1] + (bias ? bias[gc + 1] : 0.f);
                if (epilogue == 1) {
                    v0 = 0.5f * v0 * (1.f + erff(v0 * 0.7071067811865476f));
                    v1 = 0.5f * v1 * (1.f + erff(v1 * 0.7071067811865476f));
                }
                __half2 h = __floats2half2_rn(v0, v1);
                *(__half2*)(C + (size_t)(rowBase + r) * Nc + gc) = h;
            }
        } else {
            float* C = (float*)Cv;
            #pragma unroll 4
            for (int e = 0; e < 64; e++) {
                int idx = tid + e * 256;
                int r = idx >> 7, c = idx & 127;
                int gc = colBase + c;
                float v = smf[r * OSTR + c] + (bias ? bias[gc] : 0.f);
                C[(size_t)(rowBase + r) * Nc + gc] = v;
            }
        }
    } else {
        float* C = (float*)Cv;
        #pragma unroll 4
        for (int e = 0; e < 64; e++) {
            int idx = tid + e * 256;
            int r = idx >> 7, c = idx & 127;
            int gr = rowBase + r, gc = colBase + c;
            float v = smf[r * OSTR + c] + bias[gc];
            int orow = (epilogue == 2) ? map_row(gr, shifted) : gr;
            size_t off = (size_t)orow * Nc + gc;
            v += C[off];
            C[off] = v;
            if (epilogue == 3) mirror[off] = __float2half(v);
        }
    }
}

// ---------------- weight fp32 -> fp16 ----------------
__global__ void tohalf_kernel(const float4* __restrict__ in, __half* __restrict__ out, int n4) {
    int i = blockIdx.x * blockDim.x + threadIdx.x;
    if (i < n4) {
        float4 v = in[i];
        __half2* o = (__half2*)(out + i * 4);
        o[0] = __floats2half2_rn(v.x, v.y);
        o[1] = __floats2half2_rn(v.z, v.w);
    }
}

// ---------------- LayerNorm over 384 (half output) ----------------
__device__ __forceinline__ float block_sum(float v, float* sm) {
    #pragma unroll
    for (int o = 16; o; o >>= 1) v += __shfl_xor_sync(0xffffffffu, v, o);
    int w = threadIdx.x >> 5;
    if ((threadIdx.x & 31) == 0) sm[w] = v;
    __syncthreads();
    if (threadIdx.x < 32) {
        float u = (threadIdx.x < (blockDim.x >> 5)) ? sm[threadIdx.x] : 0.f;
        #pragma unroll
        for (int o = 16; o; o >>= 1) u += __shfl_xor_sync(0xffffffffu, u, o);
        if (threadIdx.x == 0) sm[0] = u;
    }
    __syncthreads();
    float r = sm[0];
    __syncthreads();
    return r;
}

__global__ void ln384_kernel(const float* __restrict__ src, __half* __restrict__ dst,
                             const float* __restrict__ g, const float* __restrict__ b,
                             int mode) {
    __shared__ float sm[8];
    int row = blockIdx.x;
    int t = (mode == 0) ? row : map_row(row, mode == 2);
    const float* sp = src + (size_t)t * DIM;
    int tx = threadIdx.x;
    float v0 = sp[tx], v1 = sp[tx + 128], v2 = sp[tx + 256];
    float m = block_sum(v0 + v1 + v2, sm) * (1.f / 384.f);
    float d0 = v0 - m, d1 = v1 - m, d2 = v2 - m;
    float var = block_sum(d0 * d0 + d1 * d1 + d2 * d2, sm) * (1.f / 384.f);
    float inv = rsqrtf(var + 1e-5f);
    __half* dp = dst + (size_t)row * DIM;
    dp[tx]       = __float2half(d0 * inv * g[tx]       + b[tx]);
    dp[tx + 128] = __float2half(d1 * inv * g[tx + 128] + b[tx + 128]);
    dp[tx + 256] = __float2half(d2 * inv * g[tx + 256] + b[tx + 256]);
}

// ---------------- windowed attention: 2 heads per 128-thread block ----------------
__global__ void attn_kernel(const __half* __restrict__ qkv, __half* __restrict__ o,
                            const float* __restrict__ rpb, int shifted) {
    __shared__ float ksm[2][49][32];
    __shared__ float vsm[2][49][32];
    __shared__ float ssm[2][49][50];
    int pair = blockIdx.x;
    int win  = pair / 6;
    int hp   = (pair % 6) * 2;
    int sub  = threadIdx.x >> 6;
    int t    = threadIdx.x & 63;
    int head = hp + sub;
    int wi = win & 63;
    int wh = wi >> 3, ww = wi & 7;
    int base = win * 49;

    for (int idx = t; idx < 49 * 32; idx += 64) {
        int j = idx >> 5, d = idx & 31;
        size_t ro = (size_t)(base + j) * QKVD + head * 32 + d;
        ksm[sub][j][d] = __half2float(qkv[ro + 384]);
        vsm[sub][j][d] = __half2float(qkv[ro + 768]);
    }
    __syncthreads();

    if (t < 49) {
        int i = t, ri = i / 7, ci = i % 7;
        float q[32];
        const __half* qp = qkv + (size_t)(base + i) * QKVD + head * 32;
        #pragma unroll
        for (int d = 0; d < 32; d++) q[d] = __half2float(qp[d]) * 0.17677669529663687f;

        int lab_i = 0;
        if (shifted) {
            int hh = wh * 7 + ri, wc = ww * 7 + ci;
            int gh = hh < 49 ? 0 : (hh < 53 ? 1 : 2);
            int gw = wc < 49 ? 0 : (wc < 53 ? 1 : 2);
            lab_i = gh * 3 + gw;
        }
        float mx = -1e30f;
        for (int j = 0; j < 49; j++) {
            float s = 0.f;
            #pragma unroll
            for (int d = 0; d < 32; d++) s += q[d] * ksm[sub][j][d];
            int rj = j / 7, cj = j % 7;
            int rpi = (ri - rj + 6) * 13 + (ci - cj + 6);
            s += rpb[rpi * 12 + head];
            if (shifted) {
                int hh = wh * 7 + rj, wc = ww * 7 + cj;
                int gh = hh < 49 ? 0 : (hh < 53 ? 1 : 2);
                int gw = wc < 49 ? 0 : (wc < 53 ? 1 : 2);
                if (gh * 3 + gw != lab_i) s -= 100.0f;
            }
            ssm[sub][i][j] = s;
            mx = fmaxf(mx, s);
        }
        float sum = 0.f;
        for (int j = 0; j < 49; j++) {
            float e = expf(ssm[sub][i][j] - mx);
            ssm[sub][i][j] = e;
            sum += e;
        }
        float inv = 1.0f / sum;
        float accv[32];
        #pragma unroll
        for (int d = 0; d < 32; d++) accv[d] = 0.f;
        for (int j = 0; j < 49; j++) {
            float p = ssm[sub][i][j] * inv;
            #pragma unroll
            for (int d = 0; d < 32; d++) accv[d] += p * vsm[sub][j][d];
        }
        __half* op = o + (size_t)(base + i) * DIM + head * 32;
        #pragma unroll
        for (int d = 0; d < 32; d++) op[d] = __float2half(accv[d]);
    }
}

// ---------------- PatchExpand pixel-shuffle + LN over 192 ----------------
__global__ void expand_ln_kernel(const float* __restrict__ e, float* __restrict__ out,
                                 const float* __restrict__ g, const float* __restrict__ b) {
    __shared__ float sm[8];
    int tt = blockIdx.x;
    int bb = tt / 12544;
    int rem = tt % 12544;
    int oh = rem / 112, ow = rem % 112;
    int h = oh >> 1, p = oh & 1, w = ow >> 1, q = ow & 1;
    int erow = bb * 3136 + h * 56 + w;
    const float* sp = e + (size_t)erow * EXPD + (p * 2 + q) * 192;
    int tx = threadIdx.x;
    float v0 = sp[tx], v1 = sp[tx + 64], v2 = sp[tx + 128];
    float m = block_sum(v0 + v1 + v2, sm) * (1.f / 192.f);
    float d0 = v0 - m, d1 = v1 - m, d2 = v2 - m;
    float var = block_sum(d0 * d0 + d1 * d1 + d2 * d2, sm) * (1.f / 192.f);
    float inv = rsqrtf(var + 1e-5f);
    float* dp = out + (size_t)tt * 192;
    dp[tx]       = d0 * inv * g[tx]       + b[tx];
    dp[tx + 64]  = d1 * inv * g[tx + 64]  + b[tx + 64];
    dp[tx + 128] = d2 * inv * g[tx + 128] + b[tx + 128];
}

__global__ void copy_kernel(float4* __restrict__ dst, const float4* __restrict__ src, int n) {
    int i = blockIdx.x * blockDim.x + threadIdx.x;
    if (i < n) dst[i] = src[i];
}

// ---------------- host orchestration ----------------
extern "C" void kernel_launch(void* const* d_in, const int* in_sizes, int n_in,
                              void* d_out, int out_size) {
    const float* x    = (const float*)d_in[0];
    const float* n1g  = (const float*)d_in[1];
    const float* n1b  = (const float*)d_in[2];
    const float* qkvw = (const float*)d_in[3];
    const float* qkvb = (const float*)d_in[4];
    const float* rpb  = (const float*)d_in[5];
    const float* pw   = (const float*)d_in[6];
    const float* pb   = (const float*)d_in[7];
    const float* n2g  = (const float*)d_in[8];
    const float* n2b  = (const float*)d_in[9];
    const float* f1w  = (const float*)d_in[10];
    const float* f1b  = (const float*)d_in[11];
    const float* f2w  = (const float*)d_in[12];
    const float* f2b  = (const float*)d_in[13];
    const float* ew   = (const float*)d_in[14];
    const float* eg   = (const float*)d_in[15];
    const float* ebv  = (const float*)d_in[16];

    float *xb, *bigb;
    __half *xh, *yh, *oh, *wh;
    cudaGetSymbolAddress((void**)&xb,   g_x);
    cudaGetSymbolAddress((void**)&xh,   g_xh);
    cudaGetSymbolAddress((void**)&yh,   g_y);
    cudaGetSymbolAddress((void**)&oh,   g_o);
    cudaGetSymbolAddress((void**)&bigb, g_big);
    cudaGetSymbolAddress((void**)&wh,   g_w);

    static int smem_set = 0;
    const int GEMM_SMEM = 128 * OSTR * sizeof(float);   // 67584 B (covers 3x18944 stages)
    if (!smem_set) {
        cudaFuncSetAttribute(gemm_fp16,
                             cudaFuncAttributeMaxDynamicSharedMemorySize, GEMM_SMEM);
        smem_set = 1;
    }

    // convert all weights to fp16 once
    tohalf_kernel<<<(884736/4 + 255)/256, 256>>>((const float4*)qkvw, wh + W_QKV, 884736/4);
    tohalf_kernel<<<(294912/4 + 255)/256, 256>>>((const float4*)pw,   wh + W_PROJ, 294912/4);
    tohalf_kernel<<<(1179648/4 + 255)/256, 256>>>((const float4*)f1w, wh + W_FC1, 1179648/4);
    tohalf_kernel<<<(1179648/4 + 255)/256, 256>>>((const float4*)f2w, wh + W_FC2, 1179648/4);
    tohalf_kernel<<<(294912/4 + 255)/256, 256>>>((const float4*)ew,   wh + W_EXP, 294912/4);

    copy_kernel<<<18816, 256>>>((float4*)xb, (const float4*)x, TOK * DIM / 4);

    const int MB = TOK / 128;   // 392 row tiles
    for (int i = 0; i < 2; i++) {
        int sh = i;
        ln384_kernel<<<TOK, 128>>>(xb, yh, n1g + i * DIM, n1b + i * DIM, sh ? 2 : 1);
        gemm_fp16<<<dim3(QKVD / 128, MB), 256, GEMM_SMEM>>>(
            yh, wh + W_QKV + (size_t)i * DIM * QKVD, qkvb + i * QKVD,
            bigb, nullptr, DIM, QKVD, 0, 0, 1);
        attn_kernel<<<1024 * 6, 128>>>((const __half*)bigb, oh, rpb + i * 169 * 12, sh);
        gemm_fp16<<<dim3(DIM / 128, MB), 256, GEMM_SMEM>>>(
            oh, wh + W_PROJ + (size_t)i * DIM * DIM, pb + i * DIM,
            xb, nullptr, DIM, DIM, 2, sh, 0);
        ln384_kernel<<<TOK, 128>>>(xb, yh, n2g + i * DIM, n2b + i * DIM, 0);
        gemm_fp16<<<dim3(FFN / 128, MB), 256, GEMM_SMEM>>>(
            yh, wh + W_FC1 + (size_t)i * DIM * FFN, f1b + i * FFN,
            bigb, nullptr, DIM, FFN, 1, 0, 1);
        gemm_fp16<<<dim3(DIM / 128, MB), 256, GEMM_SMEM>>>(
            (const __half*)bigb, wh + W_FC2 + (size_t)i * FFN * DIM, f2b + i * DIM,
            xb, xh, FFN, DIM, 3, 0, 0);
    }

    // expand GEMM reads fp16 mirror of final residual, writes fp32 for the LN
    gemm_fp16<<<dim3(EXPD / 128, MB), 256, GEMM_SMEM>>>(
        xh, wh + W_EXP, nullptr, bigb, nullptr, DIM, EXPD, 0, 0, 0);
    expand_ln_kernel<<<TOK * 4, 64>>>(bigb, (float*)d_out, eg, ebv);
}

// round 6
// speedup vs baseline: 4.1826x; 1.0972x over previous
#include <cuda_runtime.h>
#include <cuda_fp16.h>
#include <math.h>
#include <stdint.h>
#include <mma.h>
using namespace nvcuda;

// ---------------- problem constants ----------------
#define TOK   50176
#define DIM   384
#define QKVD  1152
#define FFN   1536
#define EXPD  768

// ---------------- scratch ----------------
static __device__ float  g_x  [TOK * DIM];     // fp32 residual stream
static __device__ __half g_xh [TOK * DIM];     // fp16 mirror of final residual
static __device__ __half g_y  [TOK * DIM];     // LN outputs (fp16)
static __device__ __half g_o  [TOK * DIM];     // attention out (fp16)
static __device__ float  g_big[TOK * FFN];     // qkv/mid (as half) or expand out (float)
static __device__ __half g_w  [3833856];       // fp16 weights

#define W_QKV 0
#define W_PROJ 884736
#define W_FC1 1179648
#define W_FC2 2359296
#define W_EXP 3538944

// ---------------- helpers ----------------
__device__ __forceinline__ uint32_t smem_u32(const void* p) {
    uint32_t a;
    asm("{ .reg .u64 t; cvta.to.shared.u64 t, %1; cvt.u32.u64 %0, t; }" : "=r"(a) : "l"(p));
    return a;
}
__device__ __forceinline__ void cp16(uint32_t s, const void* g) {
    asm volatile("cp.async.cg.shared.global [%0], [%1], 16;" :: "r"(s), "l"(g) : "memory");
}
#define CP_COMMIT() asm volatile("cp.async.commit_group;" ::: "memory")
#define CP_WAIT(n)  asm volatile("cp.async.wait_group %0;" :: "n"(n) : "memory")

__device__ __forceinline__ int map_row(int ridx, int shifted) {
    int n  = ridx % 49;
    int wi = (ridx / 49) & 63;
    int b  = ridx / (49 * 64);
    int r = n / 7, c = n % 7;
    int wh = wi >> 3, ww = wi & 7;
    int h = wh * 7 + r, w = ww * 7 + c;
    if (shifted) { h = (h + 3) % 56; w = (w + 3) % 56; }
    return b * 3136 + h * 56 + w;
}

// ---------------- fp16 wmma GEMM, cp.async 3-stage, BK=64 ----------------
// C = A[M,K] @ W[K,Nc] + bias.  CTA tile 128x128, 8 warps (4x2), warp 32x64.
// epilogue: 0 plain (out_half selects dtype), 1 GELU->half, 2 scatter+residual fp32,
//           3 residual fp32 + half mirror
#define ASTR 72
#define BSTR 136
#define A_STAGE (128 * ASTR)            // 9216 halves
#define B_STAGE (64 * BSTR)             // 8704 halves
#define STG (A_STAGE + B_STAGE)         // 17920 halves = 35840 B / stage
#define OSTR 132

__global__ __launch_bounds__(256, 2)
void gemm_fp16(const __half* __restrict__ A, const __half* __restrict__ W,
               const float* __restrict__ bias, void* __restrict__ Cv,
               __half* __restrict__ mirror,
               int K, int Nc, int epilogue, int shifted, int out_half) {
    extern __shared__ __align__(16) char smraw[];
    __half* smh = (__half*)smraw;
    float*  smf = (float*)smraw;
    int tid = threadIdx.x;
    int wid = tid >> 5;
    int wm = (wid & 3) * 32;
    int wn = (wid >> 2) * 64;
    int rowBase = blockIdx.y * 128;
    int colBase = blockIdx.x * 128;
    int nk = K >> 6;

    wmma::fragment<wmma::accumulator, 16, 16, 16, float> acc[2][4];
    #pragma unroll
    for (int i = 0; i < 2; i++)
        #pragma unroll
        for (int j = 0; j < 4; j++) wmma::fill_fragment(acc[i][j], 0.f);

    #define STAGE_LOAD(kt, buf) do {                                              \
        __half* As_ = smh + (buf) * STG;                                          \
        __half* Bs_ = As_ + A_STAGE;                                              \
        uint32_t as_ = smem_u32(As_), bs_ = smem_u32(Bs_);                        \
        int kg_ = (kt) * 64;                                                      \
        _Pragma("unroll")                                                         \
        for (int l = 0; l < 4; l++) {                                             \
            int c = tid + l * 256;                                                \
            int r = c >> 3, q = (c & 7) * 8;                                      \
            cp16(as_ + (uint32_t)(r * ASTR + q) * 2,                              \
                 A + (size_t)(rowBase + r) * K + kg_ + q);                        \
            int kr = c >> 4, nq = (c & 15) * 8;                                   \
            cp16(bs_ + (uint32_t)(kr * BSTR + nq) * 2,                            \
                 W + (size_t)(kg_ + kr) * Nc + colBase + nq);                     \
        }                                                                         \
    } while (0)

    STAGE_LOAD(0, 0); CP_COMMIT();
    STAGE_LOAD(1, 1); CP_COMMIT();

    for (int kt = 0; kt < nk; kt++) {
        if (kt + 2 < nk) { STAGE_LOAD(kt + 2, (kt + 2) % 3); CP_COMMIT(); CP_WAIT(2); }
        else if (kt + 1 < nk) { CP_WAIT(1); }
        else { CP_WAIT(0); }
        __syncthreads();

        const __half* As = smh + (kt % 3) * STG;
        const __half* Bs = As + A_STAGE;
        #pragma unroll
        for (int k16 = 0; k16 < 4; k16++) {
            wmma::fragment<wmma::matrix_a, 16, 16, 16, __half, wmma::row_major> af[2];
            wmma::fragment<wmma::matrix_b, 16, 16, 16, __half, wmma::row_major> bf[4];
            #pragma unroll
            for (int i = 0; i < 2; i++)
                wmma::load_matrix_sync(af[i], As + (wm + i * 16) * ASTR + k16 * 16, ASTR);
            #pragma unroll
            for (int j = 0; j < 4; j++)
                wmma::load_matrix_sync(bf[j], Bs + (k16 * 16) * BSTR + wn + j * 16, BSTR);
            #pragma unroll
            for (int i = 0; i < 2; i++)
                #pragma unroll
                for (int j = 0; j < 4; j++)
                    wmma::mma_sync(acc[i][j], af[i], bf[j], acc[i][j]);
        }
        __syncthreads();
    }

    // stage accumulators to smem as fp32
    #pragma unroll
    for (int i = 0; i < 2; i++)
        #pragma unroll
        for (int j = 0; j < 4; j++)
            wmma::store_matrix_sync(smf + (wm + i * 16) * OSTR + wn + j * 16,
                                    acc[i][j], OSTR, wmma::mem_row_major);
    __syncthreads();

    if (epilogue <= 1) {
        if (out_half) {
            __half* C = (__half*)Cv;
            #pragma unroll 4
            for (int e = 0; e < 32; e++) {
                int idx = tid + e * 256;
                int r = idx >> 6, c2 = (idx & 63) * 2;
                int gc = colBase + c2;
                float v0 = smf[r * OSTR + c2]     + (bias ? bias[gc]     : 0.f);
                float v1 = smf[r * OSTR + c2 + 1] + (bias ? bias[gc + 1] : 0.f);
                if (epilogue == 1) {
                    v0 = 0.5f * v0 * (1.f + erff(v0 * 0.7071067811865476f));
                    v1 = 0.5f * v1 * (1.f + erff(v1 * 0.7071067811865476f));
                }
                __half2 h = __floats2half2_rn(v0, v1);
                *(__half2*)(C + (size_t)(rowBase + r) * Nc + gc) = h;
            }
        } else {
            float* C = (float*)Cv;
            #pragma unroll 4
            for (int e = 0; e < 64; e++) {
                int idx = tid + e * 256;
                int r = idx >> 7, c = idx & 127;
                int gc = colBase + c;
                float v = smf[r * OSTR + c] + (bias ? bias[gc] : 0.f);
                C[(size_t)(rowBase + r) * Nc + gc] = v;
            }
        }
    } else {
        float* C = (float*)Cv;
        #pragma unroll 4
        for (int e = 0; e < 64; e++) {
            int idx = tid + e * 256;
            int r = idx >> 7, c = idx & 127;
            int gr = rowBase + r, gc = colBase + c;
            float v = smf[r * OSTR + c] + bias[gc];
            int orow = (epilogue == 2) ? map_row(gr, shifted) : gr;
            size_t off = (size_t)orow * Nc + gc;
            v += C[off];
            C[off] = v;
            if (epilogue == 3) mirror[off] = __float2half(v);
        }
    }
}

// ---------------- weight fp32 -> fp16 ----------------
__global__ void tohalf_kernel(const float4* __restrict__ in, __half* __restrict__ out, int n4) {
    int i = blockIdx.x * blockDim.x + threadIdx.x;
    if (i < n4) {
        float4 v = in[i];
        __half2* o = (__half2*)(out + i * 4);
        o[0] = __floats2half2_rn(v.x, v.y);
        o[1] = __floats2half2_rn(v.z, v.w);
    }
}

// ---------------- LayerNorm over 384 (half output) ----------------
__device__ __forceinline__ float block_sum(float v, float* sm) {
    #pragma unroll
    for (int o = 16; o; o >>= 1) v += __shfl_xor_sync(0xffffffffu, v, o);
    int w = threadIdx.x >> 5;
    if ((threadIdx.x & 31) == 0) sm[w] = v;
    __syncthreads();
    if (threadIdx.x < 32) {
        float u = (threadIdx.x < (blockDim.x >> 5)) ? sm[threadIdx.x] : 0.f;
        #pragma unroll
        for (int o = 16; o; o >>= 1) u += __shfl_xor_sync(0xffffffffu, u, o);
        if (threadIdx.x == 0) sm[0] = u;
    }
    __syncthreads();
    float r = sm[0];
    __syncthreads();
    return r;
}

__global__ void ln384_kernel(const float* __restrict__ src, __half* __restrict__ dst,
                             const float* __restrict__ g, const float* __restrict__ b,
                             int mode) {
    __shared__ float sm[8];
    int row = blockIdx.x;
    int t = (mode == 0) ? row : map_row(row, mode == 2);
    const float* sp = src + (size_t)t * DIM;
    int tx = threadIdx.x;
    float v0 = sp[tx], v1 = sp[tx + 128], v2 = sp[tx + 256];
    float m = block_sum(v0 + v1 + v2, sm) * (1.f / 384.f);
    float d0 = v0 - m, d1 = v1 - m, d2 = v2 - m;
    float var = block_sum(d0 * d0 + d1 * d1 + d2 * d2, sm) * (1.f / 384.f);
    float inv = rsqrtf(var + 1e-5f);
    __half* dp = dst + (size_t)row * DIM;
    dp[tx]       = __float2half(d0 * inv * g[tx]       + b[tx]);
    dp[tx + 128] = __float2half(d1 * inv * g[tx + 128] + b[tx + 128]);
    dp[tx + 256] = __float2half(d2 * inv * g[tx + 256] + b[tx + 256]);
}

// ---------------- windowed attention: 2 heads per 128-thread block, float4 smem ----------------
__global__ void attn_kernel(const __half* __restrict__ qkv, __half* __restrict__ o,
                            const float* __restrict__ rpb, int shifted) {
    __shared__ float4 ksm[2][49][8];
    __shared__ float4 vsm[2][49][8];
    __shared__ float  ssm[2][49][50];
    int pair = blockIdx.x;
    int win  = pair / 6;
    int hp   = (pair % 6) * 2;
    int sub  = threadIdx.x >> 6;
    int t    = threadIdx.x & 63;
    int head = hp + sub;
    int wi = win & 63;
    int wh = wi >> 3, ww = wi & 7;
    int base = win * 49;

    for (int idx = t; idx < 49 * 8; idx += 64) {
        int j = idx >> 3, d4 = idx & 7;
        size_t ro = (size_t)(base + j) * QKVD + head * 32 + d4 * 4;
        const __half2* kp = (const __half2*)(qkv + ro + 384);
        const __half2* vp = (const __half2*)(qkv + ro + 768);
        float2 k0 = __half22float2(kp[0]), k1 = __half22float2(kp[1]);
        float2 w0 = __half22float2(vp[0]), w1 = __half22float2(vp[1]);
        ksm[sub][j][d4] = make_float4(k0.x, k0.y, k1.x, k1.y);
        vsm[sub][j][d4] = make_float4(w0.x, w0.y, w1.x, w1.y);
    }
    __syncthreads();

    if (t < 49) {
        int i = t, ri = i / 7, ci = i % 7;
        float4 q[8];
        const __half2* qp = (const __half2*)(qkv + (size_t)(base + i) * QKVD + head * 32);
        #pragma unroll
        for (int d4 = 0; d4 < 8; d4++) {
            float2 a = __half22float2(qp[d4 * 2]), b = __half22float2(qp[d4 * 2 + 1]);
            const float sc = 0.17677669529663687f;
            q[d4] = make_float4(a.x * sc, a.y * sc, b.x * sc, b.y * sc);
        }

        int lab_i = 0;
        if (shifted) {
            int hh = wh * 7 + ri, wc = ww * 7 + ci;
            int gh = hh < 49 ? 0 : (hh < 53 ? 1 : 2);
            int gw = wc < 49 ? 0 : (wc < 53 ? 1 : 2);
            lab_i = gh * 3 + gw;
        }
        float mx = -1e30f;
        for (int j = 0; j < 49; j++) {
            float s = 0.f;
            #pragma unroll
            for (int d4 = 0; d4 < 8; d4++) {
                float4 kv = ksm[sub][j][d4];
                s += q[d4].x * kv.x + q[d4].y * kv.y + q[d4].z * kv.z + q[d4].w * kv.w;
            }
            int rj = j / 7, cj = j % 7;
            int rpi = (ri - rj + 6) * 13 + (ci - cj + 6);
            s += rpb[rpi * 12 + head];
            if (shifted) {
                int hh = wh * 7 + rj, wc = ww * 7 + cj;
                int gh = hh < 49 ? 0 : (hh < 53 ? 1 : 2);
                int gw = wc < 49 ? 0 : (wc < 53 ? 1 : 2);
                if (gh * 3 + gw != lab_i) s -= 100.0f;
            }
            ssm[sub][i][j] = s;
            mx = fmaxf(mx, s);
        }
        float sum = 0.f;
        for (int j = 0; j < 49; j++) {
            float e = expf(ssm[sub][i][j] - mx);
            ssm[sub][i][j] = e;
            sum += e;
        }
        float inv = 1.0f / sum;
        float4 accv[8];
        #pragma unroll
        for (int d4 = 0; d4 < 8; d4++) accv[d4] = make_float4(0.f, 0.f, 0.f, 0.f);
        for (int j = 0; j < 49; j++) {
            float p = ssm[sub][i][j] * inv;
            #pragma unroll
            for (int d4 = 0; d4 < 8; d4++) {
                float4 vv = vsm[sub][j][d4];
                accv[d4].x += p * vv.x; accv[d4].y += p * vv.y;
                accv[d4].z += p * vv.z; accv[d4].w += p * vv.w;
            }
        }
        __half2* op = (__half2*)(o + (size_t)(base + i) * DIM + head * 32);
        #pragma unroll
        for (int d4 = 0; d4 < 8; d4++) {
            op[d4 * 2]     = __floats2half2_rn(accv[d4].x, accv[d4].y);
            op[d4 * 2 + 1] = __floats2half2_rn(accv[d4].z, accv[d4].w);
        }
    }
}

// ---------------- PatchExpand pixel-shuffle + LN over 192 ----------------
__global__ void expand_ln_kernel(const float* __restrict__ e, float* __restrict__ out,
                                 const float* __restrict__ g, const float* __restrict__ b) {
    __shared__ float sm[8];
    int tt = blockIdx.x;
    int bb = tt / 12544;
    int rem = tt % 12544;
    int oh = rem / 112, ow = rem % 112;
    int h = oh >> 1, p = oh & 1, w = ow >> 1, q = ow & 1;
    int erow = bb * 3136 + h * 56 + w;
    const float* sp = e + (size_t)erow * EXPD + (p * 2 + q) * 192;
    int tx = threadIdx.x;
    float v0 = sp[tx], v1 = sp[tx + 64], v2 = sp[tx + 128];
    float m = block_sum(v0 + v1 + v2, sm) * (1.f / 192.f);
    float d0 = v0 - m, d1 = v1 - m, d2 = v2 - m;
    float var = block_sum(d0 * d0 + d1 * d1 + d2 * d2, sm) * (1.f / 192.f);
    float inv = rsqrtf(var + 1e-5f);
    float* dp = out + (size_t)tt * 192;
    dp[tx]       = d0 * inv * g[tx]       + b[tx];
    dp[tx + 64]  = d1 * inv * g[tx + 64]  + b[tx + 64];
    dp[tx + 128] = d2 * inv * g[tx + 128] + b[tx + 128];
}

__global__ void copy_kernel(float4* __restrict__ dst, const float4* __restrict__ src, int n) {
    int i = blockIdx.x * blockDim.x + threadIdx.x;
    if (i < n) dst[i] = src[i];
}

// ---------------- host orchestration ----------------
extern "C" void kernel_launch(void* const* d_in, const int* in_sizes, int n_in,
                              void* d_out, int out_size) {
    const float* x    = (const float*)d_in[0];
    const float* n1g  = (const float*)d_in[1];
    const float* n1b  = (const float*)d_in[2];
    const float* qkvw = (const float*)d_in[3];
    const float* qkvb = (const float*)d_in[4];
    const float* rpb  = (const float*)d_in[5];
    const float* pw   = (const float*)d_in[6];
    const float* pb   = (const float*)d_in[7];
    const float* n2g  = (const float*)d_in[8];
    const float* n2b  = (const float*)d_in[9];
    const float* f1w  = (const float*)d_in[10];
    const float* f1b  = (const float*)d_in[11];
    const float* f2w  = (const float*)d_in[12];
    const float* f2b  = (const float*)d_in[13];
    const float* ew   = (const float*)d_in[14];
    const float* eg   = (const float*)d_in[15];
    const float* ebv  = (const float*)d_in[16];

    float *xb, *bigb;
    __half *xh, *yh, *oh, *wh;
    cudaGetSymbolAddress((void**)&xb,   g_x);
    cudaGetSymbolAddress((void**)&xh,   g_xh);
    cudaGetSymbolAddress((void**)&yh,   g_y);
    cudaGetSymbolAddress((void**)&oh,   g_o);
    cudaGetSymbolAddress((void**)&bigb, g_big);
    cudaGetSymbolAddress((void**)&wh,   g_w);

    static int smem_set = 0;
    const int GEMM_SMEM = 3 * STG * sizeof(__half);   // 107520 B
    if (!smem_set) {
        cudaFuncSetAttribute(gemm_fp16,
                             cudaFuncAttributeMaxDynamicSharedMemorySize, GEMM_SMEM);
        smem_set = 1;
    }

    // convert all weights to fp16 once
    tohalf_kernel<<<(884736/4 + 255)/256, 256>>>((const float4*)qkvw, wh + W_QKV, 884736/4);
    tohalf_kernel<<<(294912/4 + 255)/256, 256>>>((const float4*)pw,   wh + W_PROJ, 294912/4);
    tohalf_kernel<<<(1179648/4 + 255)/256, 256>>>((const float4*)f1w, wh + W_FC1, 1179648/4);
    tohalf_kernel<<<(1179648/4 + 255)/256, 256>>>((const float4*)f2w, wh + W_FC2, 1179648/4);
    tohalf_kernel<<<(294912/4 + 255)/256, 256>>>((const float4*)ew,   wh + W_EXP, 294912/4);

    copy_kernel<<<18816, 256>>>((float4*)xb, (const float4*)x, TOK * DIM / 4);

    const int MB = TOK / 128;   // 392 row tiles
    for (int i = 0; i < 2; i++) {
        int sh = i;
        ln384_kernel<<<TOK, 128>>>(xb, yh, n1g + i * DIM, n1b + i * DIM, sh ? 2 : 1);
        gemm_fp16<<<dim3(QKVD / 128, MB), 256, GEMM_SMEM>>>(
            yh, wh + W_QKV + (size_t)i * DIM * QKVD, qkvb + i * QKVD,
            bigb, nullptr, DIM, QKVD, 0, 0, 1);
        attn_kernel<<<1024 * 6, 128>>>((const __half*)bigb, oh, rpb + i * 169 * 12, sh);
        gemm_fp16<<<dim3(DIM / 128, MB), 256, GEMM_SMEM>>>(
            oh, wh + W_PROJ + (size_t)i * DIM * DIM, pb + i * DIM,
            xb, nullptr, DIM, DIM, 2, sh, 0);
        ln384_kernel<<<TOK, 128>>>(xb, yh, n2g + i * DIM, n2b + i * DIM, 0);
        gemm_fp16<<<dim3(FFN / 128, MB), 256, GEMM_SMEM>>>(
            yh, wh + W_FC1 + (size_t)i * DIM * FFN, f1b + i * FFN,
            bigb, nullptr, DIM, FFN, 1, 0, 1);
        gemm_fp16<<<dim3(DIM / 128, MB), 256, GEMM_SMEM>>>(
            (const __half*)bigb, wh + W_FC2 + (size_t)i * FFN * DIM, f2b + i * DIM,
            xb, xh, FFN, DIM, 3, 0, 0);
    }

    // expand GEMM reads fp16 mirror of final residual, writes fp32 for the LN
    gemm_fp16<<<dim3(EXPD / 128, MB), 256, GEMM_SMEM>>>(
        xh, wh + W_EXP, nullptr, bigb, nullptr, DIM, EXPD, 0, 0, 0);
    expand_ln_kernel<<<TOK * 4, 64>>>(bigb, (float*)d_out, eg, ebv);
}